// round 11
// baseline (speedup 1.0000x reference)
#include <cuda_runtime.h>
#include <cstdint>

#define B_ 8
#define C_ 32
#define N_ 4096
#define KC 64
#define SPLIT 8
#define NSLICE (N_ / SPLIT)   // 512
#define TKN 320               // tensor-path n per slice (scalar gets 192)

__device__ float g_e[B_ * N_];
__device__ float g_part[SPLIT][2][B_ * C_ * N_];

__global__ void mean_exp_kernel(const float* __restrict__ x) {
    int idx = blockIdx.x * blockDim.x + threadIdx.x;
    if (idx >= B_ * N_) return;
    int b = idx >> 12, n = idx & (N_ - 1);
    const float* p = x + ((size_t)b * C_) * N_ + n;
    float s = 0.f;
#pragma unroll
    for (int c = 0; c < C_; c++) s += p[(size_t)c * N_];
    g_e[idx] = __expf(s * (1.0f / C_));
}

__device__ __forceinline__ uint32_t pack_f16(float hi, float lo) {
    uint32_t d;
    asm("cvt.rn.f16x2.f32 %0, %1, %2;" : "=r"(d) : "f"(hi), "f"(lo));
    return d;
}

#define MMA_F16(acc, a, b0v, b1v)                                           \
    asm volatile(                                                           \
        "mma.sync.aligned.m16n8k16.row.col.f32.f16.f16.f32 "                \
        "{%0,%1,%2,%3}, {%4,%5,%6,%7}, {%8,%9}, {%0,%1,%2,%3};"             \
        : "+f"((acc)[0]), "+f"((acc)[1]), "+f"((acc)[2]), "+f"((acc)[3])    \
        : "r"((a)[0]), "r"((a)[1]), "r"((a)[2]), "r"((a)[3]),               \
          "r"(b0v), "r"(b1v))

#define TBAR() asm volatile("bar.sync 1, 256;" ::: "memory")
#define SBAR() asm volatile("bar.sync 2, 128;" ::: "memory")

__global__ __launch_bounds__(384, 1)
void gcn_hybrid_kernel(const float* __restrict__ x,
                       const float* __restrict__ adj) {
    // tensor-path smem
    __shared__ uint32_t s_B[2][2][32 * 32];
    __shared__ float s_e[2][2][KC];
    // scalar-path smem
    __shared__ float s_sf[2][KC][36];
    __shared__ float s_se[2][KC];

    const int tid = threadIdx.x;
    const int mt = blockIdx.x;
    const int bp = blockIdx.y;
    const int b0 = 2 * bp, b1 = 2 * bp + 1;
    const int z = blockIdx.z;
    const int nbeg = z * NSLICE;

    if (tid < 256) {
        // ───────────────────────── tensor path (warps 0-7) ──────────────
        const int warp = tid >> 5;
        const int lane = tid & 31;
        const int q = lane >> 2;
        const int r = lane & 3;
        const int mb = mt * 128 + warp * 16;
        const int nend = nbeg + TKN;

        const float em0a = g_e[b0 * N_ + mb + q];
        const float em0b = g_e[b0 * N_ + mb + q + 8];
        const float em1a = g_e[b1 * N_ + mb + q];
        const float em1b = g_e[b1 * N_ + mb + q + 8];

        float acc[2][4][4];
#pragma unroll
        for (int bi = 0; bi < 2; bi++)
#pragma unroll
            for (int cf = 0; cf < 4; cf++)
#pragma unroll
                for (int i = 0; i < 4; i++) acc[bi][cf][i] = 0.f;

        const int st_b = tid >> 7;
        const int st_c = (tid >> 2) & 31;
        const int st_p0 = (tid & 3) * 8;
        const float* st_x = x + (((size_t)(2 * bp + st_b) * C_ + st_c) << 12);
        const int st_sw = 4 * (st_c & 7);

#define STAGE_STORE(BUF, U, EV)                                             \
    {                                                                       \
        uint32_t* dst = &s_B[BUF][st_b][st_c * 32];                         \
        uint32_t pr[8];                                                     \
        _Pragma("unroll")                                                   \
        for (int j = 0; j < 4; j++) {                                       \
            pr[2 * j]     = pack_f16(U[j].y, U[j].x);                       \
            pr[2 * j + 1] = pack_f16(U[j].w, U[j].z);                       \
        }                                                                   \
        *reinterpret_cast<uint4*>(&dst[(st_p0 + st_sw) & 31]) =             \
            make_uint4(pr[0], pr[1], pr[2], pr[3]);                         \
        *reinterpret_cast<uint4*>(&dst[(st_p0 + 4 + st_sw) & 31]) =         \
            make_uint4(pr[4], pr[5], pr[6], pr[7]);                         \
        if (tid < 128) s_e[BUF][tid >> 6][tid & 63] = EV;                   \
    }

#define STAGE_LOAD(U, EV, NBASE)                                            \
    {                                                                       \
        _Pragma("unroll")                                                   \
        for (int j = 0; j < 4; j++)                                         \
            U[j] = *reinterpret_cast<const float4*>(                        \
                st_x + (NBASE) + st_p0 * 2 + 4 * j);                        \
        if (tid < 128)                                                      \
            EV = g_e[(2 * bp + (tid >> 6)) * N_ + (NBASE) + (tid & 63)];    \
    }

#define PRELOAD_ADJ(G, AP, KS)                                              \
    {                                                                       \
        const float* ab = (AP) + (size_t)((KS) * 16) * N_;                  \
        G[0][0] = __ldg(ab);                                                \
        G[0][1] = __ldg(ab + 8);                                            \
        G[1][0] = __ldg(ab + (size_t)N_);                                   \
        G[1][1] = __ldg(ab + (size_t)N_ + 8);                               \
        G[2][0] = __ldg(ab + (size_t)8 * N_);                               \
        G[2][1] = __ldg(ab + (size_t)8 * N_ + 8);                           \
        G[3][0] = __ldg(ab + (size_t)9 * N_);                               \
        G[3][1] = __ldg(ab + (size_t)9 * N_ + 8);                           \
    }

#define COMPUTE_KS(G, BUF, KS)                                              \
    {                                                                       \
        const int k0 = (KS) * 16;                                           \
        float en0[4], en1[4];                                               \
        en0[0] = s_e[BUF][0][k0 + 2 * r];                                   \
        en1[0] = s_e[BUF][1][k0 + 2 * r];                                   \
        en0[1] = s_e[BUF][0][k0 + 2 * r + 1];                               \
        en1[1] = s_e[BUF][1][k0 + 2 * r + 1];                               \
        en0[2] = s_e[BUF][0][k0 + 2 * r + 8];                               \
        en1[2] = s_e[BUF][1][k0 + 2 * r + 8];                               \
        en0[3] = s_e[BUF][0][k0 + 2 * r + 9];                               \
        en1[3] = s_e[BUF][1][k0 + 2 * r + 9];                               \
        float w0[4][2], w1[4][2];                                           \
        _Pragma("unroll")                                                   \
        for (int kk = 0; kk < 4; kk++) {                                    \
            _Pragma("unroll")                                               \
            for (int mm = 0; mm < 2; mm++) {                                \
                const float e0 = mm ? em0b : em0a;                          \
                const float e1 = mm ? em1b : em1a;                          \
                float d0 = en0[kk] + e0, d1 = en1[kk] + e1;                 \
                float rr;                                                   \
                asm("rcp.approx.f32 %0, %1;" : "=f"(rr) : "f"(d0 * d1));    \
                float ra = G[kk][mm] * rr;                                  \
                w0[kk][mm] = fminf(en0[kk], e0) * d1 * ra;                  \
                w1[kk][mm] = fminf(en1[kk], e1) * d0 * ra;                  \
            }                                                               \
        }                                                                   \
        uint32_t a0[4], a1[4];                                              \
        a0[0] = pack_f16(w0[1][0], w0[0][0]);                               \
        a0[1] = pack_f16(w0[1][1], w0[0][1]);                               \
        a0[2] = pack_f16(w0[3][0], w0[2][0]);                               \
        a0[3] = pack_f16(w0[3][1], w0[2][1]);                               \
        a1[0] = pack_f16(w1[1][0], w1[0][0]);                               \
        a1[1] = pack_f16(w1[1][1], w1[0][1]);                               \
        a1[2] = pack_f16(w1[3][0], w1[2][0]);                               \
        a1[3] = pack_f16(w1[3][1], w1[2][1]);                               \
        const int kp0 = (KS) * 8;                                           \
        const int off0 = (kp0 + r + 4 * q) & 31;                            \
        const int off4 = (kp0 + r + 4 + 4 * q) & 31;                        \
        _Pragma("unroll")                                                   \
        for (int cf = 0; cf < 4; cf++) {                                    \
            const int row = (cf * 8 + q) * 32;                              \
            uint32_t b00 = s_B[BUF][0][row + off0];                         \
            uint32_t b01 = s_B[BUF][0][row + off4];                         \
            uint32_t b10 = s_B[BUF][1][row + off0];                         \
            uint32_t b11 = s_B[BUF][1][row + off4];                         \
            MMA_F16(acc[0][cf], a0, b00, b01);                              \
            MMA_F16(acc[1][cf], a1, b10, b11);                              \
        }                                                                   \
    }

        {
            float4 u[4];
            float ev = 0.f;
            STAGE_LOAD(u, ev, nbeg);
            STAGE_STORE(0, u, ev);
        }
        TBAR();

        int cur = 0;
        for (int n0 = nbeg; n0 < nend; n0 += KC) {
            const int n1 = n0 + KC;
            const bool has_next = (n1 < nend);

            float4 u[4];
            float ev = 0.f;
            if (has_next) STAGE_LOAD(u, ev, n1);

            const float* ap = adj + (size_t)(n0 + 2 * r) * N_ + mb + q;
            float gA[4][2], gB[4][2];
            PRELOAD_ADJ(gA, ap, 0);
            PRELOAD_ADJ(gB, ap, 1);
            COMPUTE_KS(gA, cur, 0);
            PRELOAD_ADJ(gA, ap, 2);
            COMPUTE_KS(gB, cur, 1);
            PRELOAD_ADJ(gB, ap, 3);
            COMPUTE_KS(gA, cur, 2);
            COMPUTE_KS(gB, cur, 3);

            if (has_next) STAGE_STORE(cur ^ 1, u, ev);
            TBAR();
            cur ^= 1;
        }

#pragma unroll
        for (int bi = 0; bi < 2; bi++) {
            float* dst = &g_part[z][0][((size_t)(2 * bp + bi) * C_) << 12];
#pragma unroll
            for (int cf = 0; cf < 4; cf++) {
                int c0 = cf * 8 + 2 * r;
                int m0 = mb + q;
                dst[((size_t)c0 << 12) + m0] = acc[bi][cf][0];
                dst[((size_t)(c0 + 1) << 12) + m0] = acc[bi][cf][1];
                dst[((size_t)c0 << 12) + m0 + 8] = acc[bi][cf][2];
                dst[((size_t)(c0 + 1) << 12) + m0 + 8] = acc[bi][cf][3];
            }
        }
    } else {
        // ───────────────────────── scalar path (warps 8-11) ─────────────
        const int stid = tid - 256;          // 0..127
        const int m = mt * 128 + stid;
        const float em0 = g_e[b0 * N_ + m];
        const float em1 = g_e[b1 * N_ + m];

        unsigned long long accA[16], accB[16];
#pragma unroll
        for (int p = 0; p < 16; p++) { accA[p] = 0ull; accB[p] = 0ull; }

        const int sg_b = stid >> 6;          // 0/1
        const int sg_i = stid & 63;          // row within chunk
        const float* sg_x = x + ((size_t)(2 * bp + sg_b) * C_) * N_;

        const int snbeg = nbeg + TKN;
        const int snend = nbeg + NSLICE;

        for (int n0 = snbeg; n0 < snend; n0 += KC) {
            SBAR();
#pragma unroll
            for (int k = 0; k < 8; k++) {
                float4 v;
                v.x = sg_x[(size_t)(4 * k + 0) * N_ + n0 + sg_i];
                v.y = sg_x[(size_t)(4 * k + 1) * N_ + n0 + sg_i];
                v.z = sg_x[(size_t)(4 * k + 2) * N_ + n0 + sg_i];
                v.w = sg_x[(size_t)(4 * k + 3) * N_ + n0 + sg_i];
                *reinterpret_cast<float4*>(&s_sf[sg_b][sg_i][4 * k]) = v;
            }
            s_se[sg_b][sg_i] = g_e[(2 * bp + sg_b) * N_ + n0 + sg_i];
            SBAR();

            const float* ap = adj + (size_t)n0 * N_ + m;
            float a_cur = __ldg(ap);
#pragma unroll 2
            for (int n = 0; n < KC; n++) {
                float a_nxt = (n + 1 < KC) ? __ldg(ap + (size_t)(n + 1) * N_) : 0.f;
                float en0 = s_se[0][n];
                float en1 = s_se[1][n];
                float d0 = en0 + em0, d1 = en1 + em1;
                float rr;
                asm("rcp.approx.f32 %0, %1;" : "=f"(rr) : "f"(d0 * d1));
                float t = a_cur * rr;
                float w0 = fminf(en0, em0) * d1 * t;
                float w1 = fminf(en1, em1) * d0 * t;
                unsigned long long w20, w21;
                asm("mov.b64 %0, {%1, %1};" : "=l"(w20) : "f"(w0));
                asm("mov.b64 %0, {%1, %1};" : "=l"(w21) : "f"(w1));
                unsigned ra0 = (unsigned)__cvta_generic_to_shared(&s_sf[0][n][0]);
                unsigned ra1 = (unsigned)__cvta_generic_to_shared(&s_sf[1][n][0]);
#pragma unroll
                for (int p = 0; p < 8; p++) {
                    unsigned long long d0v, d1v;
                    asm("ld.shared.v2.u64 {%0, %1}, [%2];"
                        : "=l"(d0v), "=l"(d1v) : "r"(ra0 + 16 * p));
                    asm("fma.rn.f32x2 %0, %1, %2, %0;"
                        : "+l"(accA[2 * p]) : "l"(d0v), "l"(w20));
                    asm("fma.rn.f32x2 %0, %1, %2, %0;"
                        : "+l"(accA[2 * p + 1]) : "l"(d1v), "l"(w20));
                }
#pragma unroll
                for (int p = 0; p < 8; p++) {
                    unsigned long long d0v, d1v;
                    asm("ld.shared.v2.u64 {%0, %1}, [%2];"
                        : "=l"(d0v), "=l"(d1v) : "r"(ra1 + 16 * p));
                    asm("fma.rn.f32x2 %0, %1, %2, %0;"
                        : "+l"(accB[2 * p]) : "l"(d0v), "l"(w21));
                    asm("fma.rn.f32x2 %0, %1, %2, %0;"
                        : "+l"(accB[2 * p + 1]) : "l"(d1v), "l"(w21));
                }
                a_cur = a_nxt;
            }
        }

        float* dst0 = &g_part[z][1][((size_t)b0 * C_) << 12] + m;
#pragma unroll
        for (int p = 0; p < 16; p++) {
            float lo, hi;
            asm("mov.b64 {%0, %1}, %2;" : "=f"(lo), "=f"(hi) : "l"(accA[p]));
            dst0[(size_t)(2 * p) << 12] = lo;
            dst0[(size_t)(2 * p + 1) << 12] = hi;
        }
        float* dst1 = &g_part[z][1][((size_t)b1 * C_) << 12] + m;
#pragma unroll
        for (int p = 0; p < 16; p++) {
            float lo, hi;
            asm("mov.b64 {%0, %1}, %2;" : "=f"(lo), "=f"(hi) : "l"(accB[p]));
            dst1[(size_t)(2 * p) << 12] = lo;
            dst1[(size_t)(2 * p + 1) << 12] = hi;
        }
    }
}

// out = relu(2 * para * sum over SPLIT x {tensor,scalar} partials)
__global__ void combine_kernel(const float* __restrict__ para,
                               float* __restrict__ out) {
    int idx = blockIdx.x * blockDim.x + threadIdx.x;
    const float4* pp = reinterpret_cast<const float4*>(para);
    const float4* parts = reinterpret_cast<const float4*>(g_part);
    const int stride = B_ * C_ * N_ / 4;
    float4 s = parts[idx];
#pragma unroll
    for (int zz = 1; zz < 2 * SPLIT; zz++) {
        float4 v = parts[(size_t)zz * stride + idx];
        s.x += v.x; s.y += v.y; s.z += v.z; s.w += v.w;
    }
    float4 pv = pp[idx & (C_ * N_ / 4 - 1)];
    float4 o;
    o.x = fmaxf(2.0f * s.x * pv.x, 0.f);
    o.y = fmaxf(2.0f * s.y * pv.y, 0.f);
    o.z = fmaxf(2.0f * s.z * pv.z, 0.f);
    o.w = fmaxf(2.0f * s.w * pv.w, 0.f);
    reinterpret_cast<float4*>(out)[idx] = o;
}

extern "C" void kernel_launch(void* const* d_in, const int* in_sizes, int n_in,
                              void* d_out, int out_size) {
    const float* x    = (const float*)d_in[0];  // [8,32,64,64]
    const float* para = (const float*)d_in[1];  // [1,32,64,64]
    const float* adj  = (const float*)d_in[2];  // [4096,4096]
    float* out = (float*)d_out;

    mean_exp_kernel<<<(B_ * N_ + 255) / 256, 256>>>(x);

    dim3 grid(N_ / 128, B_ / 2, SPLIT);
    gcn_hybrid_kernel<<<grid, 384>>>(x, adj);

    combine_kernel<<<(B_ * C_ * N_ / 4) / 256, 256>>>(para, out);
}

// round 12
// speedup vs baseline: 3.6861x; 3.6861x over previous
#include <cuda_runtime.h>
#include <cuda_fp16.h>
#include <cstdint>

#define B_ 8
#define C_ 32
#define N_ 4096
#define KC 64
#define SPLIT 4

__device__ float g_e[B_ * N_];
__device__ float g_part[SPLIT][B_ * C_ * N_];

__global__ void mean_exp_kernel(const float* __restrict__ x) {
    int idx = blockIdx.x * blockDim.x + threadIdx.x;
    if (idx >= B_ * N_) return;
    int b = idx >> 12, n = idx & (N_ - 1);
    const float* p = x + ((size_t)b * C_) * N_ + n;
    float s = 0.f;
#pragma unroll
    for (int c = 0; c < C_; c++) s += p[(size_t)c * N_];
    g_e[idx] = __expf(s * (1.0f / C_));
}

__device__ __forceinline__ uint32_t pack_f16(float hi, float lo) {
    uint32_t d;
    asm("cvt.rn.f16x2.f32 %0, %1, %2;" : "=r"(d) : "f"(hi), "f"(lo));
    return d;
}
__device__ __forceinline__ uint32_t h2u(__half2 h) {
    return *reinterpret_cast<uint32_t*>(&h);
}

#define MMA_F16(acc, a, b0v, b1v)                                           \
    asm volatile(                                                           \
        "mma.sync.aligned.m16n8k16.row.col.f32.f16.f16.f32 "                \
        "{%0,%1,%2,%3}, {%4,%5,%6,%7}, {%8,%9}, {%0,%1,%2,%3};"             \
        : "+f"((acc)[0]), "+f"((acc)[1]), "+f"((acc)[2]), "+f"((acc)[3])    \
        : "r"((a)[0]), "r"((a)[1]), "r"((a)[2]), "r"((a)[3]),               \
          "r"(b0v), "r"(b1v))

__global__ __launch_bounds__(256, 2)
void gcn_mma_kernel(const float* __restrict__ x,
                    const float* __restrict__ adj) {
    __shared__ uint32_t s_B[2][2][32 * 32];  // [buf][batch][c*32 + swz(npair)]
    __shared__ __half2 s_eh[2][KC];          // [buf][n] = (e_b0, e_b1)

    const int tid = threadIdx.x;
    const int warp = tid >> 5;
    const int lane = tid & 31;
    const int q = lane >> 2;
    const int r = lane & 3;
    const int mb = blockIdx.x * 128 + warp * 16;
    const int bp = blockIdx.y;
    const int b0 = 2 * bp, b1 = 2 * bp + 1;
    const int z = blockIdx.z;
    const int nbeg = z * (N_ / SPLIT);
    const int nend = nbeg + (N_ / SPLIT);

    // em packed across batches: [0] = rows q, [1] = rows q+8
    __half2 em_h2[2];
    em_h2[0] = __floats2half2_rn(g_e[b0 * N_ + mb + q],
                                 g_e[b1 * N_ + mb + q]);
    em_h2[1] = __floats2half2_rn(g_e[b0 * N_ + mb + q + 8],
                                 g_e[b1 * N_ + mb + q + 8]);

    float acc[2][4][4];
#pragma unroll
    for (int bi = 0; bi < 2; bi++)
#pragma unroll
        for (int cf = 0; cf < 4; cf++)
#pragma unroll
            for (int i = 0; i < 4; i++) acc[bi][cf][i] = 0.f;

    const int st_b = tid >> 7;
    const int st_c = (tid >> 2) & 31;
    const int st_p0 = (tid & 3) * 8;
    const float* st_x = x + (((size_t)(2 * bp + st_b) * C_ + st_c) << 12);
    const int st_sw = 4 * (st_c & 7);

#define STAGE_STORE(BUF, U, EV0, EV1)                                       \
    {                                                                       \
        uint32_t* dst = &s_B[BUF][st_b][st_c * 32];                         \
        uint32_t pr[8];                                                     \
        _Pragma("unroll")                                                   \
        for (int j = 0; j < 4; j++) {                                       \
            pr[2 * j]     = pack_f16(U[j].y, U[j].x);                       \
            pr[2 * j + 1] = pack_f16(U[j].w, U[j].z);                       \
        }                                                                   \
        *reinterpret_cast<uint4*>(&dst[(st_p0 + st_sw) & 31]) =             \
            make_uint4(pr[0], pr[1], pr[2], pr[3]);                         \
        *reinterpret_cast<uint4*>(&dst[(st_p0 + 4 + st_sw) & 31]) =         \
            make_uint4(pr[4], pr[5], pr[6], pr[7]);                         \
        if (tid < KC) s_eh[BUF][tid] = __floats2half2_rn(EV0, EV1);         \
    }

#define STAGE_LOAD(U, EV0, EV1, NBASE)                                      \
    {                                                                       \
        _Pragma("unroll")                                                   \
        for (int j = 0; j < 4; j++)                                         \
            U[j] = *reinterpret_cast<const float4*>(                        \
                st_x + (NBASE) + st_p0 * 2 + 4 * j);                        \
        if (tid < KC) {                                                     \
            EV0 = g_e[b0 * N_ + (NBASE) + tid];                             \
            EV1 = g_e[b1 * N_ + (NBASE) + tid];                             \
        }                                                                   \
    }

#define PRELOAD_ADJ(G, AP, KS)                                              \
    {                                                                       \
        const float* ab = (AP) + (size_t)((KS) * 16) * N_;                  \
        G[0][0] = __ldg(ab);                                                \
        G[0][1] = __ldg(ab + 8);                                            \
        G[1][0] = __ldg(ab + (size_t)N_);                                   \
        G[1][1] = __ldg(ab + (size_t)N_ + 8);                               \
        G[2][0] = __ldg(ab + (size_t)8 * N_);                               \
        G[2][1] = __ldg(ab + (size_t)8 * N_ + 8);                           \
        G[3][0] = __ldg(ab + (size_t)9 * N_);                               \
        G[3][1] = __ldg(ab + (size_t)9 * N_ + 8);                           \
    }

#define COMPUTE_KS(G, BUF, KS)                                              \
    {                                                                       \
        const int k0 = (KS) * 16;                                           \
        __half2 en[4];                                                      \
        en[0] = s_eh[BUF][k0 + 2 * r];                                      \
        en[1] = s_eh[BUF][k0 + 2 * r + 1];                                  \
        en[2] = s_eh[BUF][k0 + 2 * r + 8];                                  \
        en[3] = s_eh[BUF][k0 + 2 * r + 9];                                  \
        __half2 w[4][2];                                                    \
        _Pragma("unroll")                                                   \
        for (int kk = 0; kk < 4; kk++) {                                    \
            _Pragma("unroll")                                               \
            for (int mm = 0; mm < 2; mm++) {                                \
                __half2 e = em_h2[mm];                                      \
                __half2 d = __hadd2(en[kk], e);                             \
                __half2 mn = __hmin2(en[kk], e);                            \
                __half2 a2 = __float2half2_rn(G[kk][mm]);                   \
                w[kk][mm] = __hmul2(__hmul2(mn, h2rcp(d)), a2);             \
            }                                                               \
        }                                                                   \
        uint32_t a0[4], a1[4];                                              \
        a0[0] = h2u(__lows2half2(w[0][0], w[1][0]));                        \
        a0[1] = h2u(__lows2half2(w[0][1], w[1][1]));                        \
        a0[2] = h2u(__lows2half2(w[2][0], w[3][0]));                        \
        a0[3] = h2u(__lows2half2(w[2][1], w[3][1]));                        \
        a1[0] = h2u(__highs2half2(w[0][0], w[1][0]));                       \
        a1[1] = h2u(__highs2half2(w[0][1], w[1][1]));                       \
        a1[2] = h2u(__highs2half2(w[2][0], w[3][0]));                       \
        a1[3] = h2u(__highs2half2(w[2][1], w[3][1]));                       \
        const int kp0 = (KS) * 8;                                           \
        const int off0 = (kp0 + r + 4 * q) & 31;                            \
        const int off4 = (kp0 + r + 4 + 4 * q) & 31;                        \
        _Pragma("unroll")                                                   \
        for (int cf = 0; cf < 4; cf++) {                                    \
            const int row = (cf * 8 + q) * 32;                              \
            uint32_t b00 = s_B[BUF][0][row + off0];                         \
            uint32_t b01 = s_B[BUF][0][row + off4];                         \
            uint32_t b10 = s_B[BUF][1][row + off0];                         \
            uint32_t b11 = s_B[BUF][1][row + off4];                         \
            MMA_F16(acc[0][cf], a0, b00, b01);                              \
            MMA_F16(acc[1][cf], a1, b10, b11);                              \
        }                                                                   \
    }

    // prologue: stage first chunk
    {
        float4 u[4];
        float ev0 = 0.f, ev1 = 0.f;
        STAGE_LOAD(u, ev0, ev1, nbeg);
        STAGE_STORE(0, u, ev0, ev1);
    }
    __syncthreads();

    int cur = 0;
    for (int n0 = nbeg; n0 < nend; n0 += KC) {
        const int n1 = n0 + KC;
        const bool has_next = (n1 < nend);

        float4 u[4];
        float ev0 = 0.f, ev1 = 0.f;
        if (has_next) STAGE_LOAD(u, ev0, ev1, n1);

        const float* ap = adj + (size_t)(n0 + 2 * r) * N_ + mb + q;
        float gA[4][2], gB[4][2];
        PRELOAD_ADJ(gA, ap, 0);
        PRELOAD_ADJ(gB, ap, 1);
        COMPUTE_KS(gA, cur, 0);
        PRELOAD_ADJ(gA, ap, 2);
        COMPUTE_KS(gB, cur, 1);
        PRELOAD_ADJ(gB, ap, 3);
        COMPUTE_KS(gA, cur, 2);
        COMPUTE_KS(gB, cur, 3);

        if (has_next) STAGE_STORE(cur ^ 1, u, ev0, ev1);
        __syncthreads();
        cur ^= 1;
    }

#pragma unroll
    for (int bi = 0; bi < 2; bi++) {
        float* dst = g_part[z] + (((size_t)(2 * bp + bi) * C_) << 12);
#pragma unroll
        for (int cf = 0; cf < 4; cf++) {
            int c0 = cf * 8 + 2 * r;
            int m0 = mb + q;
            dst[((size_t)c0 << 12) + m0] = acc[bi][cf][0];
            dst[((size_t)(c0 + 1) << 12) + m0] = acc[bi][cf][1];
            dst[((size_t)c0 << 12) + m0 + 8] = acc[bi][cf][2];
            dst[((size_t)(c0 + 1) << 12) + m0 + 8] = acc[bi][cf][3];
        }
    }
}

__global__ void combine_kernel(const float* __restrict__ para,
                               float* __restrict__ out) {
    int idx = blockIdx.x * blockDim.x + threadIdx.x;
    const float4* pp = reinterpret_cast<const float4*>(para);
    float4 s = reinterpret_cast<const float4*>(g_part[0])[idx];
#pragma unroll
    for (int z = 1; z < SPLIT; z++) {
        float4 v = reinterpret_cast<const float4*>(g_part[z])[idx];
        s.x += v.x; s.y += v.y; s.z += v.z; s.w += v.w;
    }
    float4 pv = pp[idx & (C_ * N_ / 4 - 1)];
    float4 o;
    o.x = fmaxf(2.0f * s.x * pv.x, 0.f);
    o.y = fmaxf(2.0f * s.y * pv.y, 0.f);
    o.z = fmaxf(2.0f * s.z * pv.z, 0.f);
    o.w = fmaxf(2.0f * s.w * pv.w, 0.f);
    reinterpret_cast<float4*>(out)[idx] = o;
}

extern "C" void kernel_launch(void* const* d_in, const int* in_sizes, int n_in,
                              void* d_out, int out_size) {
    const float* x    = (const float*)d_in[0];  // [8,32,64,64]
    const float* para = (const float*)d_in[1];  // [1,32,64,64]
    const float* adj  = (const float*)d_in[2];  // [4096,4096]
    float* out = (float*)d_out;

    mean_exp_kernel<<<(B_ * N_ + 255) / 256, 256>>>(x);

    dim3 grid(N_ / 128, B_ / 2, SPLIT);
    gcn_mma_kernel<<<grid, 256>>>(x, adj);

    combine_kernel<<<(B_ * C_ * N_ / 4) / 256, 256>>>(para, out);
}